// round 2
// baseline (speedup 1.0000x reference)
#include <cuda_runtime.h>

#define D_ 128
#define P_ 64
#define L_ 3
#define NPOLY 2048
#define THREADS 256
// smem floats: sh 8192 | sh2 8192 | sW 4096 | sAgg 128 | sAggW 128 | sValid 64 ints
#define SMEM_BYTES ((8192 + 8192 + 4096 + 128 + 128) * 4 + 64 * 4)

typedef unsigned long long u64;

__device__ __forceinline__ u64 pack2(float a, float b) {
    u64 r; asm("mov.b64 %0, {%1, %2};" : "=l"(r) : "f"(a), "f"(b)); return r;
}
__device__ __forceinline__ void unpack2(u64 v, float& a, float& b) {
    asm("mov.b64 {%0, %1}, %2;" : "=f"(a), "=f"(b) : "l"(v));
}
// packed f32x2 FMA (FFMA2) — PTX-only, halves FFMA-pipe pressure
__device__ __forceinline__ void ffma2(u64& d, u64 a, u64 b) {
    asm("fma.rn.f32x2 %0, %1, %2, %0;" : "+l"(d) : "l"(a), "l"(b));
}

extern __shared__ float smem[];

__global__ __launch_bounds__(THREADS, 2)
void poly_mlp_kernel(const float* __restrict__ x,
                     const int* __restrict__ mask,   // bool -> int32 in harness
                     const float* __restrict__ W1, const float* __restrict__ b1,
                     const float* __restrict__ lng, const float* __restrict__ lnb,
                     const float* __restrict__ W2, const float* __restrict__ b2,
                     float* __restrict__ out)
{
    float* sh    = smem;            // [64][128] current features
    float* sh2   = smem + 8192;     // [64][128] post-LN/ReLU features
    float* sW    = smem + 16384;    // [32][128] weight tile
    float* sAgg  = smem + 20480;    // [128] masked max
    float* sAggW = smem + 20608;    // [128] agg @ W2b + b2
    int*   sValid = (int*)(smem + 20736); // [64]

    const int tid  = threadIdx.x;
    const int lane = tid & 31;
    const int warp = tid >> 5;
    const int p0   = warp * 8;          // this warp owns points p0..p0+7
    const int poly = blockIdx.x;

    // ---- mask: input True == valid point (int32 per harness dtype set) ----
    int myv = 0;
    if (tid < P_) {
        myv = (mask[poly * P_ + tid] != 0) ? 1 : 0;
        sValid[tid] = myv;
    }
    int pv = __syncthreads_or(myv);
    if (!pv) {                           // fully-invalid polygon -> zeros
        if (tid < D_) out[(size_t)poly * D_ + tid] = 0.0f;
        return;
    }

    // ---- load x[poly] into sh (64x128 f32, coalesced float4) ----
    {
        const float4* xg = (const float4*)(x + (size_t)poly * P_ * D_);
        float4* s4 = (float4*)sh;
        #pragma unroll
        for (int k = 0; k < 8; k++) s4[tid + k * THREADS] = xg[tid + k * THREADS];
    }
    // visibility guaranteed by the first __syncthreads inside the dc-loop below

    u64 acc[8][2];   // 8 points x 4 e-values (2 packed f32x2 accumulators)

    for (int i = 0; i < L_; i++) {
        const float* W1i = W1 + i * D_ * D_;
        const float* W2i = W2 + i * 2 * D_ * D_;

        // ================= GEMM1: sh @ W1 + b1 =================
        {
            float4 bv = *(const float4*)(b1 + i * D_ + lane * 4);
            u64 blo = pack2(bv.x, bv.y), bhi = pack2(bv.z, bv.w);
            #pragma unroll
            for (int p = 0; p < 8; p++) { acc[p][0] = blo; acc[p][1] = bhi; }
        }
        for (int dc = 0; dc < D_; dc += 32) {
            __syncthreads();
            {   // stage W1[dc:dc+32, :] tile (16 KB)
                const float4* Wg = (const float4*)(W1i + dc * D_);
                float4* sW4 = (float4*)sW;
                #pragma unroll
                for (int k = 0; k < 4; k++) sW4[tid + k * THREADS] = Wg[tid + k * THREADS];
            }
            __syncthreads();
            const float4* sW4 = (const float4*)sW;
            #pragma unroll
            for (int dd = 0; dd < 32; dd += 2) {
                float4 w0 = sW4[dd * 32 + lane];
                float4 w1 = sW4[dd * 32 + 32 + lane];
                u64 w0lo = pack2(w0.x, w0.y), w0hi = pack2(w0.z, w0.w);
                u64 w1lo = pack2(w1.x, w1.y), w1hi = pack2(w1.z, w1.w);
                #pragma unroll
                for (int p = 0; p < 8; p++) {
                    float2 hv = *(const float2*)(sh + (p0 + p) * D_ + dc + dd);
                    u64 ha = pack2(hv.x, hv.x);
                    u64 hb = pack2(hv.y, hv.y);
                    ffma2(acc[p][0], ha, w0lo);
                    ffma2(acc[p][1], ha, w0hi);
                    ffma2(acc[p][0], hb, w1lo);
                    ffma2(acc[p][1], hb, w1hi);
                }
            }
        }

        // ================= LayerNorm + ReLU -> sh2 =================
        {
            float4 gv = *(const float4*)(lng + i * D_ + lane * 4);
            float4 bb = *(const float4*)(lnb + i * D_ + lane * 4);
            #pragma unroll
            for (int p = 0; p < 8; p++) {
                float a0, a1, a2, a3;
                unpack2(acc[p][0], a0, a1);
                unpack2(acc[p][1], a2, a3);
                float s = a0 + a1 + a2 + a3;
                #pragma unroll
                for (int o = 16; o > 0; o >>= 1) s += __shfl_xor_sync(0xffffffffu, s, o);
                float mean = s * (1.0f / D_);
                a0 -= mean; a1 -= mean; a2 -= mean; a3 -= mean;
                float vs = a0 * a0 + a1 * a1 + a2 * a2 + a3 * a3;
                #pragma unroll
                for (int o = 16; o > 0; o >>= 1) vs += __shfl_xor_sync(0xffffffffu, vs, o);
                float rstd = rsqrtf(vs * (1.0f / D_) + 1e-5f);
                a0 = fmaxf(fmaf(a0 * rstd, gv.x, bb.x), 0.0f);
                a1 = fmaxf(fmaf(a1 * rstd, gv.y, bb.y), 0.0f);
                a2 = fmaxf(fmaf(a2 * rstd, gv.z, bb.z), 0.0f);
                a3 = fmaxf(fmaf(a3 * rstd, gv.w, bb.w), 0.0f);
                *(float4*)(sh2 + (p0 + p) * D_ + lane * 4) = make_float4(a0, a1, a2, a3);
            }
        }
        __syncthreads();

        // ================= masked max over points -> sAgg =================
        if (tid < D_) {
            float m = -INFINITY;
            #pragma unroll 8
            for (int p = 0; p < P_; p++)
                if (sValid[p]) m = fmaxf(m, sh2[p * D_ + tid]);
            sAgg[tid] = m;
        }
        __syncthreads();

        // ===== agg part of GEMM2 (same for all points): agg @ W2[128:] + b2 =====
        if (tid < D_) {
            const float* W2b = W2i + D_ * D_;
            float s = b2[i * D_ + tid];
            #pragma unroll 8
            for (int d = 0; d < D_; d++) s = fmaf(sAgg[d], W2b[d * D_ + tid], s);
            sAggW[tid] = s;
        }
        __syncthreads();

        // ================= GEMM2 main: sh2 @ W2[:128] + sAggW -> sh =================
        {
            float4 aw = *(const float4*)(sAggW + lane * 4);
            u64 alo = pack2(aw.x, aw.y), ahi = pack2(aw.z, aw.w);
            #pragma unroll
            for (int p = 0; p < 8; p++) { acc[p][0] = alo; acc[p][1] = ahi; }
        }
        for (int dc = 0; dc < D_; dc += 32) {
            __syncthreads();
            {   // stage W2a[dc:dc+32, :] tile
                const float4* Wg = (const float4*)(W2i + dc * D_);
                float4* sW4 = (float4*)sW;
                #pragma unroll
                for (int k = 0; k < 4; k++) sW4[tid + k * THREADS] = Wg[tid + k * THREADS];
            }
            __syncthreads();
            const float4* sW4 = (const float4*)sW;
            #pragma unroll
            for (int dd = 0; dd < 32; dd += 2) {
                float4 w0 = sW4[dd * 32 + lane];
                float4 w1 = sW4[dd * 32 + 32 + lane];
                u64 w0lo = pack2(w0.x, w0.y), w0hi = pack2(w0.z, w0.w);
                u64 w1lo = pack2(w1.x, w1.y), w1hi = pack2(w1.z, w1.w);
                #pragma unroll
                for (int p = 0; p < 8; p++) {
                    float2 hv = *(const float2*)(sh2 + (p0 + p) * D_ + dc + dd);
                    u64 ha = pack2(hv.x, hv.x);
                    u64 hb = pack2(hv.y, hv.y);
                    ffma2(acc[p][0], ha, w0lo);
                    ffma2(acc[p][1], ha, w0hi);
                    ffma2(acc[p][0], hb, w1lo);
                    ffma2(acc[p][1], hb, w1hi);
                }
            }
        }
        // write back to sh (each warp writes only rows it reads next layer)
        #pragma unroll
        for (int p = 0; p < 8; p++) {
            float a0, a1, a2, a3;
            unpack2(acc[p][0], a0, a1);
            unpack2(acc[p][1], a2, a3);
            *(float4*)(sh + (p0 + p) * D_ + lane * 4) = make_float4(a0, a1, a2, a3);
        }
    }

    __syncthreads();
    // ---- final masked max over points -> out ----
    if (tid < D_) {
        float m = -INFINITY;
        #pragma unroll 8
        for (int p = 0; p < P_; p++)
            if (sValid[p]) m = fmaxf(m, sh[p * D_ + tid]);
        out[(size_t)poly * D_ + tid] = m;
    }
}

extern "C" void kernel_launch(void* const* d_in, const int* in_sizes, int n_in,
                              void* d_out, int out_size) {
    const float* x    = (const float*)d_in[0];
    const int*   mask = (const int*)d_in[1];
    const float* W1   = (const float*)d_in[2];
    const float* b1   = (const float*)d_in[3];
    const float* lng  = (const float*)d_in[4];
    const float* lnb  = (const float*)d_in[5];
    const float* W2   = (const float*)d_in[6];
    const float* b2   = (const float*)d_in[7];
    float*       out  = (float*)d_out;

    cudaFuncSetAttribute(poly_mlp_kernel,
                         cudaFuncAttributeMaxDynamicSharedMemorySize, SMEM_BYTES);
    poly_mlp_kernel<<<NPOLY, THREADS, SMEM_BYTES>>>(x, mask, W1, b1, lng, lnb, W2, b2, out);
}

// round 4
// speedup vs baseline: 1.4284x; 1.4284x over previous
#include <cuda_runtime.h>
#include <cstdint>

#define NPAIR 1024
#define THREADS 128

// ---- float-index smem offsets ----
#define SA    0        // A fragments: [mt(8)][kt(16)][lane(32)][4] = 16384 floats
#define SB0   16384    // B fragments (W1):  [nt(16)][kt(16)][lane(32)][2]
#define SB1   32768    // B fragments (W2a)
#define B1S   49152
#define GS    49280
#define BTS   49408
#define SAW0  49536
#define SAW1  49664
#define AGG0  49792
#define AGG1  49920
#define PART  50048    // [warp(4)][col(128)]
#define MASKI 50560    // 128 ints
#define PVI   50688    // 2 ints
#define SMEM_BYTES (50696 * 4)

// pre-permuted, tf32-rounded weight fragment images
__device__ __align__(256) float gBW1[3 * 16384];
__device__ __align__(256) float gBW2[3 * 16384];

__device__ __forceinline__ uint32_t to_tf32(float x) {
    uint32_t r; asm("cvt.rna.tf32.f32 %0, %1;" : "=r"(r) : "f"(x)); return r;
}
__device__ __forceinline__ float to_tf32f(float x) { return __uint_as_float(to_tf32(x)); }

__device__ __forceinline__ uint32_t smem_u32(const void* p) {
    uint32_t a; asm("{ .reg .u64 t; cvta.to.shared.u64 t, %1; cvt.u32.u64 %0, t; }" : "=r"(a) : "l"(p));
    return a;
}
__device__ __forceinline__ void mma8(float* c, uint32_t a0, uint32_t a1, uint32_t a2, uint32_t a3,
                                     uint32_t b0, uint32_t b1) {
    asm("mma.sync.aligned.m16n8k8.row.col.f32.tf32.tf32.f32 "
        "{%0,%1,%2,%3}, {%4,%5,%6,%7}, {%8,%9}, {%0,%1,%2,%3};"
        : "+f"(c[0]), "+f"(c[1]), "+f"(c[2]), "+f"(c[3])
        : "r"(a0), "r"(a1), "r"(a2), "r"(a3), "r"(b0), "r"(b1));
}
// 64KB async copy: 128 threads x 32 x 16B
__device__ __forceinline__ void cp_issue64k(uint32_t dst, const float* src, int tid) {
    #pragma unroll
    for (int k = 0; k < 32; k++)
        asm volatile("cp.async.cg.shared.global [%0], [%1], 16;"
                     :: "r"(dst + (uint32_t)(tid + k * 128) * 16u), "l"(src + (tid + k * 128) * 4)
                     : "memory");
    asm volatile("cp.async.commit_group;" ::: "memory");
}
__device__ __forceinline__ void cp_wait1() { asm volatile("cp.async.wait_group 1;" ::: "memory"); }
__device__ __forceinline__ void cp_wait0() { asm volatile("cp.async.wait_group 0;" ::: "memory"); }

// ---------- prep: build fragment-layout tf32 weight images ----------
// B frag (m16n8k8, .col): b0: k=t, n=g ; b1: k=t+4, n=g ; lane=g*4+t
// dst[((nt*16+kt)*32+lane)*2 + j] = tf32(W[kt*8+t+j*4][nt*8+g])
__global__ void prep_kernel(const float* __restrict__ W1, const float* __restrict__ W2) {
    int b = blockIdx.x;            // 0..5
    int layer = b >> 1, isW2 = b & 1;
    const float* src = isW2 ? (W2 + layer * 256 * 128) : (W1 + layer * 128 * 128);
    float* dst = isW2 ? (gBW2 + layer * 16384) : (gBW1 + layer * 16384);
    for (int idx = threadIdx.x; idx < 16384; idx += blockDim.x) {
        int j = idx & 1, lane = (idx >> 1) & 31, kt = (idx >> 6) & 15, nt = idx >> 10;
        int g = lane >> 2, t = lane & 3;
        int k = kt * 8 + t + j * 4;
        int n = nt * 8 + g;
        dst[idx] = to_tf32f(src[k * 128 + n]);
    }
}

// A slot memory order per lane: [a0, a2, a1, a3]
// writer (thread=row r, col c): mt=r>>4, g=r&15 -> lane=(g&7)*4+(c&3), slot=((c&7)>=4)+2*(g>=8)
__device__ __forceinline__ void gemm128(const float* sm, int sBoff, int lid, int warp,
                                        float acc[2][16][4]) {
    #pragma unroll
    for (int m = 0; m < 2; m++)
        #pragma unroll
        for (int nt = 0; nt < 16; nt++)
            #pragma unroll
            for (int j = 0; j < 4; j++) acc[m][nt][j] = 0.0f;
    const int mt0 = warp * 2, mt1 = mt0 + 1;
    #pragma unroll 1
    for (int kt = 0; kt < 16; kt++) {
        uint4 A0 = *(const uint4*)(sm + SA + ((mt0 * 16 + kt) * 32 + lid) * 4);
        uint4 A1 = *(const uint4*)(sm + SA + ((mt1 * 16 + kt) * 32 + lid) * 4);
        #pragma unroll
        for (int nt = 0; nt < 16; nt++) {
            uint2 B = *(const uint2*)(sm + sBoff + ((nt * 16 + kt) * 32 + lid) * 2);
            // mem order [a0,a2,a1,a3] -> operands {a0,a1,a2,a3} = {x,z,y,w}
            mma8(acc[0][nt], A0.x, A0.z, A0.y, A0.w, B.x, B.y);
            mma8(acc[1][nt], A1.x, A1.z, A1.y, A1.w, B.x, B.y);
        }
    }
}

extern __shared__ float smem[];

__global__ __launch_bounds__(THREADS, 1)
void poly_mma_kernel(const float* __restrict__ x, const int* __restrict__ mask,
                     const float* __restrict__ b1,
                     const float* __restrict__ lng, const float* __restrict__ lnb,
                     const float* __restrict__ W2, const float* __restrict__ b2,
                     float* __restrict__ out)
{
    const int tid = threadIdx.x;
    const int lid = tid & 31;
    const int warp = tid >> 5;
    const int gq = lid >> 2, tq = lid & 3;
    const int bid = blockIdx.x;
    int* sMask = (int*)(smem + MASKI);
    int* sPv   = (int*)(smem + PVI);
    const uint32_t sb0_a = smem_u32(smem) + SB0 * 4;
    const uint32_t sb1_a = smem_u32(smem) + SB1 * 4;

    // prefetch W1 layer0
    cp_issue64k(sb0_a, gBW1, tid);

    sMask[tid] = mask[bid * 128 + tid];
    __syncthreads();
    if (tid < 2) {
        int pv = 0;
        #pragma unroll 8
        for (int p = 0; p < 64; p++) pv |= sMask[tid * 64 + p];
        sPv[tid] = pv;
    }
    __syncthreads();

    // ---- load x row -> A fragments (tf32) ----
    {
        float hx[128];
        const float4* xr = (const float4*)(x + ((size_t)bid * 128 + tid) * 128);
        const int pvMine = sPv[tid >> 6];
        #pragma unroll
        for (int k = 0; k < 32; k++) {
            float4 v = xr[k];
            if (!pvMine) { v.x = 0; v.y = 0; v.z = 0; v.w = 0; }
            hx[4*k] = v.x; hx[4*k+1] = v.y; hx[4*k+2] = v.z; hx[4*k+3] = v.w;
        }
        const int mt = tid >> 4, g = tid & 15, gl = g & 7, jb = (g >> 3) * 2;
        #pragma unroll
        for (int kt = 0; kt < 16; kt++)
            #pragma unroll
            for (int t = 0; t < 4; t++) {
                int base = SA + ((mt * 16 + kt) * 32 + gl * 4 + t) * 4 + jb;
                smem[base]     = to_tf32f(hx[kt * 8 + t]);       // a0 / a1
                smem[base + 1] = to_tf32f(hx[kt * 8 + t + 4]);   // a2 / a3
            }
    }

    float acc[2][16][4];
    const int pvW = 0; // placeholder (re-read per layer via sPv)

    for (int layer = 0; layer < 3; layer++) {
        // per-layer vectors + prefetch W2a
        smem[B1S + tid] = b1[layer * 128 + tid];
        smem[GS  + tid] = lng[layer * 128 + tid];
        smem[BTS + tid] = lnb[layer * 128 + tid];
        cp_issue64k(sb1_a, gBW2 + layer * 16384, tid);
        cp_wait1();
        __syncthreads();          // sB0 (W1) + vectors ready

        // ===== GEMM1 =====
        gemm128(smem, SB0, lid, warp, acc);

        // ===== epilogue 1: +b1, LN, ReLU; store A frags; partial col-max =====
        {
            const int myPv = sPv[warp >> 1];
            bool vld[2][2];
            #pragma unroll
            for (int mt = 0; mt < 2; mt++)
                #pragma unroll
                for (int sb = 0; sb < 2; sb++) {
                    int r = warp * 32 + mt * 16 + gq + sb * 8;
                    vld[mt][sb] = myPv ? (sMask[r] != 0) : true;
                }
            float sum[2][2] = {{0,0},{0,0}};
            #pragma unroll
            for (int mt = 0; mt < 2; mt++)
                #pragma unroll
                for (int nt = 0; nt < 16; nt++) {
                    int c0 = nt * 8 + 2 * tq;
                    float b0v = smem[B1S + c0], b1v = smem[B1S + c0 + 1];
                    acc[mt][nt][0] += b0v; acc[mt][nt][1] += b1v;
                    acc[mt][nt][2] += b0v; acc[mt][nt][3] += b1v;
                    sum[mt][0] += acc[mt][nt][0] + acc[mt][nt][1];
                    sum[mt][1] += acc[mt][nt][2] + acc[mt][nt][3];
                }
            float mean[2][2], rstd[2][2];
            #pragma unroll
            for (int mt = 0; mt < 2; mt++)
                #pragma unroll
                for (int sb = 0; sb < 2; sb++) {
                    float s = sum[mt][sb];
                    s += __shfl_xor_sync(0xffffffffu, s, 1);
                    s += __shfl_xor_sync(0xffffffffu, s, 2);
                    mean[mt][sb] = s * (1.0f / 128.0f);
                }
            float var[2][2] = {{0,0},{0,0}};
            #pragma unroll
            for (int mt = 0; mt < 2; mt++)
                #pragma unroll
                for (int nt = 0; nt < 16; nt++) {
                    float d0 = acc[mt][nt][0] - mean[mt][0], d1 = acc[mt][nt][1] - mean[mt][0];
                    float d2 = acc[mt][nt][2] - mean[mt][1], d3 = acc[mt][nt][3] - mean[mt][1];
                    var[mt][0] += d0 * d0 + d1 * d1;
                    var[mt][1] += d2 * d2 + d3 * d3;
                }
            #pragma unroll
            for (int mt = 0; mt < 2; mt++)
                #pragma unroll
                for (int sb = 0; sb < 2; sb++) {
                    float s = var[mt][sb];
                    s += __shfl_xor_sync(0xffffffffu, s, 1);
                    s += __shfl_xor_sync(0xffffffffu, s, 2);
                    rstd[mt][sb] = rsqrtf(s * (1.0f / 128.0f) + 1e-5f);
                }
            float pm[16][2];
            #pragma unroll
            for (int nt = 0; nt < 16; nt++) { pm[nt][0] = -INFINITY; pm[nt][1] = -INFINITY; }
            #pragma unroll
            for (int mt = 0; mt < 2; mt++)
                #pragma unroll
                for (int nt = 0; nt < 16; nt++) {
                    int c0 = nt * 8 + 2 * tq;
                    float g0 = smem[GS + c0], g1 = smem[GS + c0 + 1];
                    float t0 = smem[BTS + c0], t1 = smem[BTS + c0 + 1];
                    #pragma unroll
                    for (int idx = 0; idx < 4; idx++) {
                        int sb = idx >> 1, o = idx & 1;
                        float hv = fmaxf(fmaf((acc[mt][nt][idx] - mean[mt][sb]) * rstd[mt][sb],
                                              o ? g1 : g0, o ? t1 : t0), 0.0f);
                        int lane_t = ((2 * tq) & 3) + o;
                        int slot = (tq >= 2 ? 1 : 0) + (sb ? 2 : 0);
                        smem[SA + (((warp * 2 + mt) * 16 + nt) * 32 + gq * 4 + lane_t) * 4 + slot]
                            = to_tf32f(hv);
                        float mv = vld[mt][sb] ? hv : -INFINITY;
                        pm[nt][o] = fmaxf(pm[nt][o], mv);
                    }
                }
            #pragma unroll
            for (int nt = 0; nt < 16; nt++) {
                #pragma unroll
                for (int off = 4; off <= 16; off <<= 1) {
                    pm[nt][0] = fmaxf(pm[nt][0], __shfl_xor_sync(0xffffffffu, pm[nt][0], off));
                    pm[nt][1] = fmaxf(pm[nt][1], __shfl_xor_sync(0xffffffffu, pm[nt][1], off));
                }
                if (gq == 0) {
                    smem[PART + warp * 128 + nt * 8 + 2 * tq]     = pm[nt][0];
                    smem[PART + warp * 128 + nt * 8 + 2 * tq + 1] = pm[nt][1];
                }
            }
        }
        __syncthreads();
        // agg per poly
        {
            float a0 = fmaxf(smem[PART + tid], smem[PART + 128 + tid]);
            float a1 = fmaxf(smem[PART + 256 + tid], smem[PART + 384 + tid]);
            smem[AGG0 + tid] = a0;
            smem[AGG1 + tid] = a1;
        }
        __syncthreads();
        // aggW = b2 + agg @ W2b
        {
            float s0 = b2[layer * 128 + tid], s1 = s0;
            const float* w2b = W2 + layer * 256 * 128 + 128 * 128 + tid;
            #pragma unroll 8
            for (int d = 0; d < 128; d++) {
                float w = __ldg(w2b + d * 128);
                s0 = fmaf(smem[AGG0 + d], w, s0);
                s1 = fmaf(smem[AGG1 + d], w, s1);
            }
            smem[SAW0 + tid] = s0;
            smem[SAW1 + tid] = s1;
        }
        if (layer < 2) { cp_issue64k(sb0_a, gBW1 + (layer + 1) * 16384, tid); cp_wait1(); }
        else           { cp_wait0(); }
        __syncthreads();          // sB1 (W2a) + saw ready

        // ===== GEMM2 =====
        gemm128(smem, SB1, lid, warp, acc);

        // ===== epilogue 2: + aggW ; store A frags (or final partial max) =====
        {
            const float* saw = smem + (warp < 2 ? SAW0 : SAW1);
            if (layer < 2) {
                #pragma unroll
                for (int mt = 0; mt < 2; mt++)
                    #pragma unroll
                    for (int nt = 0; nt < 16; nt++) {
                        int c0 = nt * 8 + 2 * tq;
                        float w0 = saw[c0], w1 = saw[c0 + 1];
                        #pragma unroll
                        for (int idx = 0; idx < 4; idx++) {
                            int sb = idx >> 1, o = idx & 1;
                            float v = acc[mt][nt][idx] + (o ? w1 : w0);
                            int lane_t = ((2 * tq) & 3) + o;
                            int slot = (tq >= 2 ? 1 : 0) + (sb ? 2 : 0);
                            smem[SA + (((warp * 2 + mt) * 16 + nt) * 32 + gq * 4 + lane_t) * 4 + slot]
                                = to_tf32f(v);
                        }
                    }
            } else {
                const int myPv = sPv[warp >> 1];
                bool vld[2][2];
                #pragma unroll
                for (int mt = 0; mt < 2; mt++)
                    #pragma unroll
                    for (int sb = 0; sb < 2; sb++) {
                        int r = warp * 32 + mt * 16 + gq + sb * 8;
                        vld[mt][sb] = myPv ? (sMask[r] != 0) : true;
                    }
                float pm[16][2];
                #pragma unroll
                for (int nt = 0; nt < 16; nt++) { pm[nt][0] = -INFINITY; pm[nt][1] = -INFINITY; }
                #pragma unroll
                for (int mt = 0; mt < 2; mt++)
                    #pragma unroll
                    for (int nt = 0; nt < 16; nt++) {
                        int c0 = nt * 8 + 2 * tq;
                        float w0 = saw[c0], w1 = saw[c0 + 1];
                        #pragma unroll
                        for (int idx = 0; idx < 4; idx++) {
                            int sb = idx >> 1, o = idx & 1;
                            float v = acc[mt][nt][idx] + (o ? w1 : w0);
                            float mv = vld[mt][sb] ? v : -INFINITY;
                            pm[nt][o] = fmaxf(pm[nt][o], mv);
                        }
                    }
                #pragma unroll
                for (int nt = 0; nt < 16; nt++) {
                    #pragma unroll
                    for (int off = 4; off <= 16; off <<= 1) {
                        pm[nt][0] = fmaxf(pm[nt][0], __shfl_xor_sync(0xffffffffu, pm[nt][0], off));
                        pm[nt][1] = fmaxf(pm[nt][1], __shfl_xor_sync(0xffffffffu, pm[nt][1], off));
                    }
                    if (gq == 0) {
                        smem[PART + warp * 128 + nt * 8 + 2 * tq]     = pm[nt][0];
                        smem[PART + warp * 128 + nt * 8 + 2 * tq + 1] = pm[nt][1];
                    }
                }
            }
        }
    }

    __syncthreads();
    {
        float m0 = fmaxf(smem[PART + tid], smem[PART + 128 + tid]);
        float m1 = fmaxf(smem[PART + 256 + tid], smem[PART + 384 + tid]);
        out[(size_t)(bid * 2)     * 128 + tid] = sPv[0] ? m0 : 0.0f;
        out[(size_t)(bid * 2 + 1) * 128 + tid] = sPv[1] ? m1 : 0.0f;
    }
    (void)pvW;
}

extern "C" void kernel_launch(void* const* d_in, const int* in_sizes, int n_in,
                              void* d_out, int out_size) {
    const float* x    = (const float*)d_in[0];
    const int*   mask = (const int*)d_in[1];
    const float* W1   = (const float*)d_in[2];
    const float* b1   = (const float*)d_in[3];
    const float* lng  = (const float*)d_in[4];
    const float* lnb  = (const float*)d_in[5];
    const float* W2   = (const float*)d_in[6];
    const float* b2   = (const float*)d_in[7];
    float*       out  = (float*)d_out;

    prep_kernel<<<6, 256>>>(W1, W2);

    cudaFuncSetAttribute(poly_mma_kernel,
                         cudaFuncAttributeMaxDynamicSharedMemorySize, SMEM_BYTES);
    poly_mma_kernel<<<NPAIR, THREADS, SMEM_BYTES>>>(x, mask, b1, lng, lnb, W2, b2, out);
}

// round 5
// speedup vs baseline: 1.6838x; 1.1788x over previous
#include <cuda_runtime.h>
#include <cstdint>

#define NPAIR 1024
#define THREADS 256

// ---- float-index smem offsets ----
#define SA    0        // A fragments: [mt(8)][kt(16)][lane(32)][4]
#define SB0   16384    // B fragments (W1)
#define SB1   32768    // B fragments (W2a)
#define B1S   49152
#define GS    49280
#define BTS   49408
#define SAW   49536    // [2][128]
#define PART  49792    // [mg(4)][col(128)]
#define SUMS  50304    // float2 [ng(2)][row(128)]
#define MASKI 50816    // 128 ints
#define PVI   50944    // 2 ints
#define SMEM_BYTES (50952 * 4)

__device__ __align__(256) float gBW1[3 * 16384];
__device__ __align__(256) float gBW2[3 * 16384];

__device__ __forceinline__ uint32_t to_tf32(float x) {
    uint32_t r; asm("cvt.rna.tf32.f32 %0, %1;" : "=r"(r) : "f"(x)); return r;
}
__device__ __forceinline__ float to_tf32f(float x) { return __uint_as_float(to_tf32(x)); }

__device__ __forceinline__ uint32_t smem_u32(const void* p) {
    uint32_t a; asm("{ .reg .u64 t; cvta.to.shared.u64 t, %1; cvt.u32.u64 %0, t; }" : "=r"(a) : "l"(p));
    return a;
}
__device__ __forceinline__ void mma8(float* c, uint32_t a0, uint32_t a1, uint32_t a2, uint32_t a3,
                                     uint32_t b0, uint32_t b1) {
    asm("mma.sync.aligned.m16n8k8.row.col.f32.tf32.tf32.f32 "
        "{%0,%1,%2,%3}, {%4,%5,%6,%7}, {%8,%9}, {%0,%1,%2,%3};"
        : "+f"(c[0]), "+f"(c[1]), "+f"(c[2]), "+f"(c[3])
        : "r"(a0), "r"(a1), "r"(a2), "r"(a3), "r"(b0), "r"(b1));
}
// 64KB async copy: 256 threads x 16 x 16B
__device__ __forceinline__ void cp_issue64k(uint32_t dst, const float* src, int tid) {
    #pragma unroll
    for (int k = 0; k < 16; k++)
        asm volatile("cp.async.cg.shared.global [%0], [%1], 16;"
                     :: "r"(dst + (uint32_t)(tid + k * 256) * 16u), "l"(src + (tid + k * 256) * 4)
                     : "memory");
    asm volatile("cp.async.commit_group;" ::: "memory");
}
__device__ __forceinline__ void cp_wait1() { asm volatile("cp.async.wait_group 1;" ::: "memory"); }
__device__ __forceinline__ void cp_wait0() { asm volatile("cp.async.wait_group 0;" ::: "memory"); }

// ---------- prep: fragment-layout tf32 weight images ----------
__global__ void prep_kernel(const float* __restrict__ W1, const float* __restrict__ W2) {
    int b = blockIdx.x;            // 0..5
    int layer = b >> 1, isW2 = b & 1;
    const float* src = isW2 ? (W2 + layer * 256 * 128) : (W1 + layer * 128 * 128);
    float* dst = isW2 ? (gBW2 + layer * 16384) : (gBW1 + layer * 16384);
    for (int idx = threadIdx.x; idx < 16384; idx += blockDim.x) {
        int j = idx & 1, lane = (idx >> 1) & 31, kt = (idx >> 6) & 15, nt = idx >> 10;
        int g = lane >> 2, t = lane & 3;
        dst[idx] = to_tf32f(src[(kt * 8 + t + j * 4) * 128 + nt * 8 + g]);
    }
}

extern __shared__ float smem[];

// warp (mg,ng): rows mg*32..+31 (mt = mg*2, mg*2+1), cols ng*64..+63 (nt = ng*8+ntl)
__device__ __forceinline__ void gemm64(const float* sm, int sBoff, int lid, int mg, int ng,
                                       float acc[2][8][4]) {
    #pragma unroll
    for (int m = 0; m < 2; m++)
        #pragma unroll
        for (int nt = 0; nt < 8; nt++)
            #pragma unroll
            for (int j = 0; j < 4; j++) acc[m][nt][j] = 0.0f;
    const int mt0 = mg * 2, mt1 = mt0 + 1;
    #pragma unroll 1
    for (int kt = 0; kt < 16; kt++) {
        uint4 A0 = *(const uint4*)(sm + SA + ((mt0 * 16 + kt) * 32 + lid) * 4);
        uint4 A1 = *(const uint4*)(sm + SA + ((mt1 * 16 + kt) * 32 + lid) * 4);
        #pragma unroll
        for (int ntl = 0; ntl < 8; ntl++) {
            int nt = ng * 8 + ntl;
            uint2 B = *(const uint2*)(sm + sBoff + ((nt * 16 + kt) * 32 + lid) * 2);
            mma8(acc[0][ntl], A0.x, A0.z, A0.y, A0.w, B.x, B.y);
            mma8(acc[1][ntl], A1.x, A1.z, A1.y, A1.w, B.x, B.y);
        }
    }
}

__global__ __launch_bounds__(THREADS, 1)
void poly_mma_kernel(const float* __restrict__ x, const int* __restrict__ mask,
                     const float* __restrict__ b1,
                     const float* __restrict__ lng, const float* __restrict__ lnb,
                     const float* __restrict__ W2, const float* __restrict__ b2,
                     float* __restrict__ out)
{
    const int tid = threadIdx.x;
    const int lid = tid & 31;
    const int warp = tid >> 5;
    const int mg = warp >> 1, ng = warp & 1;
    const int gq = lid >> 2, tq = lid & 3;
    const int bid = blockIdx.x;
    int* sMask = (int*)(smem + MASKI);
    int* sPv   = (int*)(smem + PVI);
    const uint32_t sb0_a = smem_u32(smem) + SB0 * 4;
    const uint32_t sb1_a = smem_u32(smem) + SB1 * 4;

    cp_issue64k(sb0_a, gBW1, tid);       // G0: W1 layer0

    if (tid < 128) sMask[tid] = mask[bid * 128 + tid];
    __syncthreads();
    if (tid < 2) {
        int pv = 0;
        #pragma unroll 8
        for (int p = 0; p < 64; p++) pv |= sMask[tid * 64 + p];
        sPv[tid] = pv;
    }
    __syncthreads();

    // ---- load x: thread = (row, col-half) -> A fragments (tf32) ----
    {
        const int row = tid >> 1, half = tid & 1;
        float hx[64];
        const float4* xr = (const float4*)(x + ((size_t)bid * 128 + row) * 128 + half * 64);
        const int pvMine = sPv[row >> 6];
        #pragma unroll
        for (int k = 0; k < 16; k++) {
            float4 v = xr[k];
            if (!pvMine) { v.x = 0; v.y = 0; v.z = 0; v.w = 0; }
            hx[4*k] = v.x; hx[4*k+1] = v.y; hx[4*k+2] = v.z; hx[4*k+3] = v.w;
        }
        const int mt = row >> 4, g = row & 15, gl = g & 7, jb = (g >> 3) * 2;
        #pragma unroll
        for (int ktl = 0; ktl < 8; ktl++) {
            int kt = half * 8 + ktl;
            #pragma unroll
            for (int t = 0; t < 4; t++) {
                int base = SA + ((mt * 16 + kt) * 32 + gl * 4 + t) * 4 + jb;
                smem[base]     = to_tf32f(hx[ktl * 8 + t]);
                smem[base + 1] = to_tf32f(hx[ktl * 8 + t + 4]);
            }
        }
    }

    float acc[2][8][4];
    const int myPv = 0; (void)myPv;

    for (int layer = 0; layer < 3; layer++) {
        if (tid < 128) {
            smem[B1S + tid] = b1[layer * 128 + tid];
            smem[GS  + tid] = lng[layer * 128 + tid];
            smem[BTS + tid] = lnb[layer * 128 + tid];
        }
        cp_issue64k(sb1_a, gBW2 + layer * 16384, tid);   // W2a layer
        cp_wait1();
        __syncthreads();                                  // S1: SB0, vectors, SA

        // ===== GEMM1 =====
        gemm64(smem, SB0, lid, mg, ng, acc);

        // ===== epilogue 1 =====
        {
            const int pvMine = sPv[mg >> 1];
            bool vld[2][2];
            #pragma unroll
            for (int mt = 0; mt < 2; mt++)
                #pragma unroll
                for (int sb = 0; sb < 2; sb++) {
                    int r = mg * 32 + mt * 16 + gq + sb * 8;
                    vld[mt][sb] = pvMine ? (sMask[r] != 0) : true;
                }
            float s[2][2] = {{0,0},{0,0}}, q[2][2] = {{0,0},{0,0}};
            #pragma unroll
            for (int mt = 0; mt < 2; mt++)
                #pragma unroll
                for (int ntl = 0; ntl < 8; ntl++) {
                    int c0 = ng * 64 + ntl * 8 + 2 * tq;
                    float b0v = smem[B1S + c0], b1v = smem[B1S + c0 + 1];
                    float* a = acc[mt][ntl];
                    a[0] += b0v; a[1] += b1v; a[2] += b0v; a[3] += b1v;
                    s[mt][0] += a[0] + a[1]; q[mt][0] += a[0]*a[0] + a[1]*a[1];
                    s[mt][1] += a[2] + a[3]; q[mt][1] += a[2]*a[2] + a[3]*a[3];
                }
            #pragma unroll
            for (int mt = 0; mt < 2; mt++)
                #pragma unroll
                for (int sb = 0; sb < 2; sb++) {
                    s[mt][sb] += __shfl_xor_sync(0xffffffffu, s[mt][sb], 1);
                    s[mt][sb] += __shfl_xor_sync(0xffffffffu, s[mt][sb], 2);
                    q[mt][sb] += __shfl_xor_sync(0xffffffffu, q[mt][sb], 1);
                    q[mt][sb] += __shfl_xor_sync(0xffffffffu, q[mt][sb], 2);
                }
            if (tq == 0) {
                float2* su = (float2*)(smem + SUMS);
                #pragma unroll
                for (int mt = 0; mt < 2; mt++)
                    #pragma unroll
                    for (int sb = 0; sb < 2; sb++) {
                        int r = mg * 32 + mt * 16 + gq + sb * 8;
                        su[ng * 128 + r] = make_float2(s[mt][sb], q[mt][sb]);
                    }
            }
            __syncthreads();                               // S2: sums (all GEMM1 reads done)
            float mean[2][2], rstd[2][2];
            {
                const float2* su = (const float2*)(smem + SUMS);
                #pragma unroll
                for (int mt = 0; mt < 2; mt++)
                    #pragma unroll
                    for (int sb = 0; sb < 2; sb++) {
                        int r = mg * 32 + mt * 16 + gq + sb * 8;
                        float2 u = su[r], v = su[128 + r];
                        float m = (u.x + v.x) * (1.0f / 128.0f);
                        float var = (u.y + v.y) * (1.0f / 128.0f) - m * m;
                        mean[mt][sb] = m;
                        rstd[mt][sb] = rsqrtf(var + 1e-5f);
                    }
            }
            float pm[8][2];
            #pragma unroll
            for (int ntl = 0; ntl < 8; ntl++) { pm[ntl][0] = -INFINITY; pm[ntl][1] = -INFINITY; }
            #pragma unroll
            for (int mt = 0; mt < 2; mt++)
                #pragma unroll
                for (int ntl = 0; ntl < 8; ntl++) {
                    int nt = ng * 8 + ntl;
                    int c0 = nt * 8 + 2 * tq;
                    float g0 = smem[GS + c0], g1 = smem[GS + c0 + 1];
                    float t0 = smem[BTS + c0], t1 = smem[BTS + c0 + 1];
                    #pragma unroll
                    for (int idx = 0; idx < 4; idx++) {
                        int sb = idx >> 1, o = idx & 1;
                        float hv = fmaxf(fmaf((acc[mt][ntl][idx] - mean[mt][sb]) * rstd[mt][sb],
                                              o ? g1 : g0, o ? t1 : t0), 0.0f);
                        int lane_t = ((2 * tq) & 3) + o;
                        int slot = (tq >= 2 ? 1 : 0) + (sb ? 2 : 0);
                        smem[SA + (((mg * 2 + mt) * 16 + nt) * 32 + gq * 4 + lane_t) * 4 + slot]
                            = to_tf32f(hv);
                        pm[ntl][o] = fmaxf(pm[ntl][o], vld[mt][sb] ? hv : -INFINITY);
                    }
                }
            #pragma unroll
            for (int ntl = 0; ntl < 8; ntl++) {
                #pragma unroll
                for (int off = 4; off <= 16; off <<= 1) {
                    pm[ntl][0] = fmaxf(pm[ntl][0], __shfl_xor_sync(0xffffffffu, pm[ntl][0], off));
                    pm[ntl][1] = fmaxf(pm[ntl][1], __shfl_xor_sync(0xffffffffu, pm[ntl][1], off));
                }
                if (gq == 0) {
                    smem[PART + mg * 128 + ng * 64 + ntl * 8 + 2 * tq]     = pm[ntl][0];
                    smem[PART + mg * 128 + ng * 64 + ntl * 8 + 2 * tq + 1] = pm[ntl][1];
                }
            }
        }
        __syncthreads();                                    // S3: PART ready

        // ---- aggW = b2 + (max over points) @ W2b, 256 threads ----
        {
            int poly = tid >> 7, col = tid & 127;
            float sacc = b2[layer * 128 + col];
            const float* w2b = W2 + layer * 256 * 128 + 128 * 128 + col;
            const float* p0 = smem + PART + poly * 256;
            #pragma unroll 8
            for (int d = 0; d < 128; d++) {
                float a = fmaxf(p0[d], p0[128 + d]);
                sacc = fmaf(a, __ldg(w2b + d * 128), sacc);
            }
            smem[SAW + poly * 128 + col] = sacc;
        }
        if (layer < 2) { cp_issue64k(sb0_a, gBW1 + (layer + 1) * 16384, tid); cp_wait1(); }
        else           { cp_wait0(); }
        __syncthreads();                                    // S4: SAW + SB1 ready

        // ===== GEMM2 =====
        gemm64(smem, SB1, lid, mg, ng, acc);

        // ===== epilogue 2 =====
        {
            const float* saw = smem + SAW + (mg >> 1) * 128;
            if (layer < 2) {
                #pragma unroll
                for (int mt = 0; mt < 2; mt++)
                    #pragma unroll
                    for (int ntl = 0; ntl < 8; ntl++) {
                        int nt = ng * 8 + ntl;
                        int c0 = nt * 8 + 2 * tq;
                        float w0 = saw[c0], w1 = saw[c0 + 1];
                        #pragma unroll
                        for (int idx = 0; idx < 4; idx++) {
                            int sb = idx >> 1, o = idx & 1;
                            float v = acc[mt][ntl][idx] + (o ? w1 : w0);
                            int lane_t = ((2 * tq) & 3) + o;
                            int slot = (tq >= 2 ? 1 : 0) + (sb ? 2 : 0);
                            smem[SA + (((mg * 2 + mt) * 16 + nt) * 32 + gq * 4 + lane_t) * 4 + slot]
                                = to_tf32f(v);
                        }
                    }
            } else {
                const int pvMine = sPv[mg >> 1];
                bool vld[2][2];
                #pragma unroll
                for (int mt = 0; mt < 2; mt++)
                    #pragma unroll
                    for (int sb = 0; sb < 2; sb++) {
                        int r = mg * 32 + mt * 16 + gq + sb * 8;
                        vld[mt][sb] = pvMine ? (sMask[r] != 0) : true;
                    }
                float pm[8][2];
                #pragma unroll
                for (int ntl = 0; ntl < 8; ntl++) { pm[ntl][0] = -INFINITY; pm[ntl][1] = -INFINITY; }
                #pragma unroll
                for (int mt = 0; mt < 2; mt++)
                    #pragma unroll
                    for (int ntl = 0; ntl < 8; ntl++) {
                        int c0 = ng * 64 + ntl * 8 + 2 * tq;
                        float w0 = saw[c0], w1 = saw[c0 + 1];
                        #pragma unroll
                        for (int idx = 0; idx < 4; idx++) {
                            int sb = idx >> 1, o = idx & 1;
                            float v = acc[mt][ntl][idx] + (o ? w1 : w0);
                            pm[ntl][o] = fmaxf(pm[ntl][o], vld[mt][sb] ? v : -INFINITY);
                        }
                    }
                #pragma unroll
                for (int ntl = 0; ntl < 8; ntl++) {
                    #pragma unroll
                    for (int off = 4; off <= 16; off <<= 1) {
                        pm[ntl][0] = fmaxf(pm[ntl][0], __shfl_xor_sync(0xffffffffu, pm[ntl][0], off));
                        pm[ntl][1] = fmaxf(pm[ntl][1], __shfl_xor_sync(0xffffffffu, pm[ntl][1], off));
                    }
                    if (gq == 0) {
                        smem[PART + mg * 128 + ng * 64 + ntl * 8 + 2 * tq]     = pm[ntl][0];
                        smem[PART + mg * 128 + ng * 64 + ntl * 8 + 2 * tq + 1] = pm[ntl][1];
                    }
                }
            }
        }
        __syncthreads();                                    // S5: SB1/SA safe to reuse, PART ready
    }

    {
        int poly = tid >> 7, col = tid & 127;
        float m = fmaxf(smem[PART + poly * 256 + col], smem[PART + poly * 256 + 128 + col]);
        out[(size_t)(bid * 2 + poly) * 128 + col] = sPv[poly] ? m : 0.0f;
    }
}

extern "C" void kernel_launch(void* const* d_in, const int* in_sizes, int n_in,
                              void* d_out, int out_size) {
    const float* x    = (const float*)d_in[0];
    const int*   mask = (const int*)d_in[1];
    const float* W1   = (const float*)d_in[2];
    const float* b1   = (const float*)d_in[3];
    const float* lng  = (const float*)d_in[4];
    const float* lnb  = (const float*)d_in[5];
    const float* W2   = (const float*)d_in[6];
    const float* b2   = (const float*)d_in[7];
    float*       out  = (float*)d_out;

    prep_kernel<<<6, 256>>>(W1, W2);

    cudaFuncSetAttribute(poly_mma_kernel,
                         cudaFuncAttributeMaxDynamicSharedMemorySize, SMEM_BYTES);
    poly_mma_kernel<<<NPAIR, THREADS, SMEM_BYTES>>>(x, mask, b1, lng, lnb, W2, b2, out);
}

// round 6
// speedup vs baseline: 2.0797x; 1.2351x over previous
#include <cuda_runtime.h>
#include <cstdint>

#define NPAIR 1024
#define THREADS 256

// ---- float-index smem offsets (compact: ~71 KB) ----
#define SA    0        // A fragments: [mt(8)][kt(16)][lane(32)][4]
#define B1S   16384
#define GS    16512
#define BTS   16640
#define SAW   16768    // [2][128]
#define PART  17024    // [mg(4)][col(128)]
#define SUMS  17536    // float2 [ng(2)][row(128)]
#define MASKI 18048    // 128 ints
#define PVI   18176    // 2 ints
#define SMEM_BYTES (18184 * 4)

__device__ __align__(256) float gBW1[3 * 16384];
__device__ __align__(256) float gBW2[3 * 16384];

__device__ __forceinline__ uint32_t to_tf32(float x) {
    uint32_t r; asm("cvt.rna.tf32.f32 %0, %1;" : "=r"(r) : "f"(x)); return r;
}
__device__ __forceinline__ float to_tf32f(float x) { return __uint_as_float(to_tf32(x)); }

__device__ __forceinline__ void mma8(float* c, uint32_t a0, uint32_t a1, uint32_t a2, uint32_t a3,
                                     uint32_t b0, uint32_t b1) {
    asm("mma.sync.aligned.m16n8k8.row.col.f32.tf32.tf32.f32 "
        "{%0,%1,%2,%3}, {%4,%5,%6,%7}, {%8,%9}, {%0,%1,%2,%3};"
        : "+f"(c[0]), "+f"(c[1]), "+f"(c[2]), "+f"(c[3])
        : "r"(a0), "r"(a1), "r"(a2), "r"(a3), "r"(b0), "r"(b1));
}

// ---------- prep: fragment-layout tf32 weight images ----------
__global__ void prep_kernel(const float* __restrict__ W1, const float* __restrict__ W2) {
    int b = blockIdx.x;            // 0..5
    int layer = b >> 1, isW2 = b & 1;
    const float* src = isW2 ? (W2 + layer * 256 * 128) : (W1 + layer * 128 * 128);
    float* dst = isW2 ? (gBW2 + layer * 16384) : (gBW1 + layer * 16384);
    for (int idx = threadIdx.x; idx < 16384; idx += blockDim.x) {
        int j = idx & 1, lane = (idx >> 1) & 31, kt = (idx >> 6) & 15, nt = idx >> 10;
        int g = lane >> 2, t = lane & 3;
        dst[idx] = to_tf32f(src[(kt * 8 + t + j * 4) * 128 + nt * 8 + g]);
    }
}

extern __shared__ float smem[];

// warp (mg,ng): rows mg*32..+31, cols ng*64..+63. B fragments streamed from L2 via LDG.
__device__ __forceinline__ void gemm64(const float* sm, const float* gB, int lid, int mg, int ng,
                                       float acc[2][8][4]) {
    #pragma unroll
    for (int m = 0; m < 2; m++)
        #pragma unroll
        for (int nt = 0; nt < 8; nt++)
            #pragma unroll
            for (int j = 0; j < 4; j++) acc[m][nt][j] = 0.0f;
    const int mt0 = mg * 2, mt1 = mt0 + 1;
    const float* base = gB + ng * 8192 + lid * 2;
    uint2 Bk[8];
    #pragma unroll
    for (int ntl = 0; ntl < 8; ntl++) Bk[ntl] = __ldg((const uint2*)(base + ntl * 1024));
    #pragma unroll 1
    for (int kt = 0; kt < 16; kt++) {
        const int ktn = (kt + 1 < 16) ? kt + 1 : 15;
        uint2 Bn[8];
        #pragma unroll
        for (int ntl = 0; ntl < 8; ntl++)
            Bn[ntl] = __ldg((const uint2*)(base + ntl * 1024 + ktn * 64));
        uint4 A0 = *(const uint4*)(sm + SA + ((mt0 * 16 + kt) * 32 + lid) * 4);
        uint4 A1 = *(const uint4*)(sm + SA + ((mt1 * 16 + kt) * 32 + lid) * 4);
        #pragma unroll
        for (int ntl = 0; ntl < 8; ntl++) {
            mma8(acc[0][ntl], A0.x, A0.z, A0.y, A0.w, Bk[ntl].x, Bk[ntl].y);
            mma8(acc[1][ntl], A1.x, A1.z, A1.y, A1.w, Bk[ntl].x, Bk[ntl].y);
        }
        #pragma unroll
        for (int ntl = 0; ntl < 8; ntl++) Bk[ntl] = Bn[ntl];
    }
}

__global__ __launch_bounds__(THREADS, 2)
void poly_mma_kernel(const float* __restrict__ x, const int* __restrict__ mask,
                     const float* __restrict__ b1,
                     const float* __restrict__ lng, const float* __restrict__ lnb,
                     const float* __restrict__ W2, const float* __restrict__ b2,
                     float* __restrict__ out)
{
    const int tid = threadIdx.x;
    const int lid = tid & 31;
    const int warp = tid >> 5;
    const int mg = warp >> 1, ng = warp & 1;
    const int gq = lid >> 2, tq = lid & 3;
    const int bid = blockIdx.x;
    int* sMask = (int*)(smem + MASKI);
    int* sPv   = (int*)(smem + PVI);

    if (tid < 128) sMask[tid] = mask[bid * 128 + tid];
    __syncthreads();
    if (tid < 2) {
        int pv = 0;
        #pragma unroll 8
        for (int p = 0; p < 64; p++) pv |= sMask[tid * 64 + p];
        sPv[tid] = pv;
    }
    __syncthreads();

    // ---- load x: thread = (row, col-half) -> A fragments (tf32) ----
    {
        const int row = tid >> 1, half = tid & 1;
        float hx[64];
        const float4* xr = (const float4*)(x + ((size_t)bid * 128 + row) * 128 + half * 64);
        const int pvMine = sPv[row >> 6];
        #pragma unroll
        for (int k = 0; k < 16; k++) {
            float4 v = xr[k];
            if (!pvMine) { v.x = 0; v.y = 0; v.z = 0; v.w = 0; }
            hx[4*k] = v.x; hx[4*k+1] = v.y; hx[4*k+2] = v.z; hx[4*k+3] = v.w;
        }
        const int mt = row >> 4, g = row & 15, gl = g & 7, jb = (g >> 3) * 2;
        #pragma unroll
        for (int ktl = 0; ktl < 8; ktl++) {
            int kt = half * 8 + ktl;
            #pragma unroll
            for (int t = 0; t < 4; t++) {
                int base = SA + ((mt * 16 + kt) * 32 + gl * 4 + t) * 4 + jb;
                smem[base]     = to_tf32f(hx[ktl * 8 + t]);
                smem[base + 1] = to_tf32f(hx[ktl * 8 + t + 4]);
            }
        }
    }

    float acc[2][8][4];

    for (int layer = 0; layer < 3; layer++) {
        if (tid < 128) {
            smem[B1S + tid] = b1[layer * 128 + tid];
            smem[GS  + tid] = lng[layer * 128 + tid];
            smem[BTS + tid] = lnb[layer * 128 + tid];
        }
        __syncthreads();                                  // S1: SA + vectors ready

        // ===== GEMM1: h @ W1 (B from L2) =====
        gemm64(smem, gBW1 + layer * 16384, lid, mg, ng, acc);

        // ===== epilogue 1: +b1, LN, ReLU; SA write; partial col-max =====
        {
            const int pvMine = sPv[mg >> 1];
            bool vld[2][2];
            #pragma unroll
            for (int mt = 0; mt < 2; mt++)
                #pragma unroll
                for (int sb = 0; sb < 2; sb++) {
                    int r = mg * 32 + mt * 16 + gq + sb * 8;
                    vld[mt][sb] = pvMine ? (sMask[r] != 0) : true;
                }
            float s[2][2] = {{0,0},{0,0}}, q[2][2] = {{0,0},{0,0}};
            #pragma unroll
            for (int mt = 0; mt < 2; mt++)
                #pragma unroll
                for (int ntl = 0; ntl < 8; ntl++) {
                    int c0 = ng * 64 + ntl * 8 + 2 * tq;
                    float b0v = smem[B1S + c0], b1v = smem[B1S + c0 + 1];
                    float* a = acc[mt][ntl];
                    a[0] += b0v; a[1] += b1v; a[2] += b0v; a[3] += b1v;
                    s[mt][0] += a[0] + a[1]; q[mt][0] += a[0]*a[0] + a[1]*a[1];
                    s[mt][1] += a[2] + a[3]; q[mt][1] += a[2]*a[2] + a[3]*a[3];
                }
            #pragma unroll
            for (int mt = 0; mt < 2; mt++)
                #pragma unroll
                for (int sb = 0; sb < 2; sb++) {
                    s[mt][sb] += __shfl_xor_sync(0xffffffffu, s[mt][sb], 1);
                    s[mt][sb] += __shfl_xor_sync(0xffffffffu, s[mt][sb], 2);
                    q[mt][sb] += __shfl_xor_sync(0xffffffffu, q[mt][sb], 1);
                    q[mt][sb] += __shfl_xor_sync(0xffffffffu, q[mt][sb], 2);
                }
            if (tq == 0) {
                float2* su = (float2*)(smem + SUMS);
                #pragma unroll
                for (int mt = 0; mt < 2; mt++)
                    #pragma unroll
                    for (int sb = 0; sb < 2; sb++) {
                        int r = mg * 32 + mt * 16 + gq + sb * 8;
                        su[ng * 128 + r] = make_float2(s[mt][sb], q[mt][sb]);
                    }
            }
            __syncthreads();                               // S2: sums ready; GEMM1 reads done
            float mean[2][2], rstd[2][2];
            {
                const float2* su = (const float2*)(smem + SUMS);
                #pragma unroll
                for (int mt = 0; mt < 2; mt++)
                    #pragma unroll
                    for (int sb = 0; sb < 2; sb++) {
                        int r = mg * 32 + mt * 16 + gq + sb * 8;
                        float2 u = su[r], v = su[128 + r];
                        float m = (u.x + v.x) * (1.0f / 128.0f);
                        float var = (u.y + v.y) * (1.0f / 128.0f) - m * m;
                        mean[mt][sb] = m;
                        rstd[mt][sb] = rsqrtf(var + 1e-5f);
                    }
            }
            float pm[8][2];
            #pragma unroll
            for (int ntl = 0; ntl < 8; ntl++) { pm[ntl][0] = -INFINITY; pm[ntl][1] = -INFINITY; }
            #pragma unroll
            for (int mt = 0; mt < 2; mt++)
                #pragma unroll
                for (int ntl = 0; ntl < 8; ntl++) {
                    int nt = ng * 8 + ntl;
                    int c0 = nt * 8 + 2 * tq;
                    float g0 = smem[GS + c0], g1 = smem[GS + c0 + 1];
                    float t0 = smem[BTS + c0], t1 = smem[BTS + c0 + 1];
                    #pragma unroll
                    for (int idx = 0; idx < 4; idx++) {
                        int sb = idx >> 1, o = idx & 1;
                        float hv = fmaxf(fmaf((acc[mt][ntl][idx] - mean[mt][sb]) * rstd[mt][sb],
                                              o ? g1 : g0, o ? t1 : t0), 0.0f);
                        int lane_t = ((2 * tq) & 3) + o;
                        int slot = (tq >= 2 ? 1 : 0) + (sb ? 2 : 0);
                        smem[SA + (((mg * 2 + mt) * 16 + nt) * 32 + gq * 4 + lane_t) * 4 + slot]
                            = to_tf32f(hv);
                        pm[ntl][o] = fmaxf(pm[ntl][o], vld[mt][sb] ? hv : -INFINITY);
                    }
                }
            #pragma unroll
            for (int ntl = 0; ntl < 8; ntl++) {
                #pragma unroll
                for (int off = 4; off <= 16; off <<= 1) {
                    pm[ntl][0] = fmaxf(pm[ntl][0], __shfl_xor_sync(0xffffffffu, pm[ntl][0], off));
                    pm[ntl][1] = fmaxf(pm[ntl][1], __shfl_xor_sync(0xffffffffu, pm[ntl][1], off));
                }
                if (gq == 0) {
                    smem[PART + mg * 128 + ng * 64 + ntl * 8 + 2 * tq]     = pm[ntl][0];
                    smem[PART + mg * 128 + ng * 64 + ntl * 8 + 2 * tq + 1] = pm[ntl][1];
                }
            }
        }
        __syncthreads();                                    // S3: PART + SA(h2) ready

        // ---- aggW = b2 + (max over points) @ W2b, 256 threads ----
        {
            int poly = tid >> 7, col = tid & 127;
            float sacc = b2[layer * 128 + col];
            const float* w2b = W2 + layer * 256 * 128 + 128 * 128 + col;
            const float* p0 = smem + PART + poly * 256;
            #pragma unroll 8
            for (int d = 0; d < 128; d++) {
                float a = fmaxf(p0[d], p0[128 + d]);
                sacc = fmaf(a, __ldg(w2b + d * 128), sacc);
            }
            smem[SAW + poly * 128 + col] = sacc;
        }
        __syncthreads();                                    // S4: SAW ready

        // ===== GEMM2: h2 @ W2a (B from L2) =====
        gemm64(smem, gBW2 + layer * 16384, lid, mg, ng, acc);
        __syncthreads();                                    // S4b: all GEMM2 SA reads done

        // ===== epilogue 2: + aggW ; SA write (or final partial max) =====
        {
            const float* saw = smem + SAW + (mg >> 1) * 128;
            if (layer < 2) {
                #pragma unroll
                for (int mt = 0; mt < 2; mt++)
                    #pragma unroll
                    for (int ntl = 0; ntl < 8; ntl++) {
                        int nt = ng * 8 + ntl;
                        int c0 = nt * 8 + 2 * tq;
                        float w0 = saw[c0], w1 = saw[c0 + 1];
                        #pragma unroll
                        for (int idx = 0; idx < 4; idx++) {
                            int sb = idx >> 1, o = idx & 1;
                            float v = acc[mt][ntl][idx] + (o ? w1 : w0);
                            int lane_t = ((2 * tq) & 3) + o;
                            int slot = (tq >= 2 ? 1 : 0) + (sb ? 2 : 0);
                            smem[SA + (((mg * 2 + mt) * 16 + nt) * 32 + gq * 4 + lane_t) * 4 + slot]
                                = to_tf32f(v);
                        }
                    }
            } else {
                const int pvMine = sPv[mg >> 1];
                bool vld[2][2];
                #pragma unroll
                for (int mt = 0; mt < 2; mt++)
                    #pragma unroll
                    for (int sb = 0; sb < 2; sb++) {
                        int r = mg * 32 + mt * 16 + gq + sb * 8;
                        vld[mt][sb] = pvMine ? (sMask[r] != 0) : true;
                    }
                float pm[8][2];
                #pragma unroll
                for (int ntl = 0; ntl < 8; ntl++) { pm[ntl][0] = -INFINITY; pm[ntl][1] = -INFINITY; }
                #pragma unroll
                for (int mt = 0; mt < 2; mt++)
                    #pragma unroll
                    for (int ntl = 0; ntl < 8; ntl++) {
                        int c0 = ng * 64 + ntl * 8 + 2 * tq;
                        float w0 = saw[c0], w1 = saw[c0 + 1];
                        #pragma unroll
                        for (int idx = 0; idx < 4; idx++) {
                            int sb = idx >> 1, o = idx & 1;
                            float v = acc[mt][ntl][idx] + (o ? w1 : w0);
                            pm[ntl][o] = fmaxf(pm[ntl][o], vld[mt][sb] ? v : -INFINITY);
                        }
                    }
                #pragma unroll
                for (int ntl = 0; ntl < 8; ntl++) {
                    #pragma unroll
                    for (int off = 4; off <= 16; off <<= 1) {
                        pm[ntl][0] = fmaxf(pm[ntl][0], __shfl_xor_sync(0xffffffffu, pm[ntl][0], off));
                        pm[ntl][1] = fmaxf(pm[ntl][1], __shfl_xor_sync(0xffffffffu, pm[ntl][1], off));
                    }
                    if (gq == 0) {
                        smem[PART + mg * 128 + ng * 64 + ntl * 8 + 2 * tq]     = pm[ntl][0];
                        smem[PART + mg * 128 + ng * 64 + ntl * 8 + 2 * tq + 1] = pm[ntl][1];
                    }
                }
            }
        }
        __syncthreads();                                    // S5: SA/PART ready for next phase
    }

    {
        int poly = tid >> 7, col = tid & 127;
        float m = fmaxf(smem[PART + poly * 256 + col], smem[PART + poly * 256 + 128 + col]);
        out[(size_t)(bid * 2 + poly) * 128 + col] = sPv[poly] ? m : 0.0f;
    }
}

extern "C" void kernel_launch(void* const* d_in, const int* in_sizes, int n_in,
                              void* d_out, int out_size) {
    const float* x    = (const float*)d_in[0];
    const int*   mask = (const int*)d_in[1];
    const float* W1   = (const float*)d_in[2];
    const float* b1   = (const float*)d_in[3];
    const float* lng  = (const float*)d_in[4];
    const float* lnb  = (const float*)d_in[5];
    const float* W2   = (const float*)d_in[6];
    const float* b2   = (const float*)d_in[7];
    float*       out  = (float*)d_out;

    prep_kernel<<<6, 256>>>(W1, W2);

    cudaFuncSetAttribute(poly_mma_kernel,
                         cudaFuncAttributeMaxDynamicSharedMemorySize, SMEM_BYTES);
    poly_mma_kernel<<<NPAIR, THREADS, SMEM_BYTES>>>(x, mask, b1, lng, lnb, W2, b2, out);
}